// round 1
// baseline (speedup 1.0000x reference)
#include <cuda_runtime.h>
#include <math.h>

// Problem constants (fixed by reference)
#define B_   2
#define HH   56
#define WW   56
#define C_   256
#define NH   8
#define HD   32
#define TOK  (B_*HH*WW)      // 6272
#define POS  (HH*WW)         // 3136
#define QSCALE 0.17677669529663687f   // 32^-0.5

// Stage buffers (device globals — no runtime allocation)
__device__ float g_q[B_*NH*POS*HD];
__device__ float g_k[B_*NH*POS*HD];
__device__ float g_v[B_*NH*POS*HD];
__device__ float g_att[TOK*C_];

// ---------------------------------------------------------------------------
// Tiled fp32 GEMM config: 64x64 block tile, BK=16, 256 threads, 4x4 per thread
// ---------------------------------------------------------------------------
#define BM 64
#define BN 64
#define BK 16
#define TM 4
#define TN 4

// QKV GEMM + scatter into g_q/g_k/g_v with q pre-scaled.
// A: [TOK, 256] (x), Bw: [256, 768] (w_qkv), bias: [768]
__global__ void qkv_gemm_kernel(const float* __restrict__ A,
                                const float* __restrict__ Bw,
                                const float* __restrict__ bias)
{
    __shared__ float As[BK][BM+4];
    __shared__ float Bs[BK][BN+4];

    const int tid  = threadIdx.x;
    const int row0 = blockIdx.y * BM;
    const int col0 = blockIdx.x * BN;
    const int K = C_;
    const int N = 3*C_;

    float acc[TM][TN];
    #pragma unroll
    for (int m = 0; m < TM; m++)
        #pragma unroll
        for (int n = 0; n < TN; n++)
            acc[m][n] = 0.0f;

    const int ty = tid / 16;
    const int tx = tid % 16;

    for (int k0 = 0; k0 < K; k0 += BK) {
        #pragma unroll
        for (int j = 0; j < (BM*BK)/256; j++) {
            int i = tid + j*256;
            int r = i / BK, c = i % BK;
            As[c][r] = A[(long)(row0 + r)*K + (k0 + c)];
        }
        #pragma unroll
        for (int j = 0; j < (BK*BN)/256; j++) {
            int i = tid + j*256;
            int r = i / BN, c = i % BN;
            Bs[r][c] = Bw[(long)(k0 + r)*N + (col0 + c)];
        }
        __syncthreads();

        #pragma unroll
        for (int kk = 0; kk < BK; kk++) {
            float ra[TM], rb[TN];
            #pragma unroll
            for (int m = 0; m < TM; m++) ra[m] = As[kk][ty*TM + m];
            #pragma unroll
            for (int n = 0; n < TN; n++) rb[n] = Bs[kk][tx*TN + n];
            #pragma unroll
            for (int m = 0; m < TM; m++)
                #pragma unroll
                for (int n = 0; n < TN; n++)
                    acc[m][n] += ra[m] * rb[n];
        }
        __syncthreads();
    }

    // Scatter: column j -> (t, h, d);  t=j/256, h=(j/32)%8, d=j%32
    #pragma unroll
    for (int m = 0; m < TM; m++) {
        int gm  = row0 + ty*TM + m;          // token index
        int b   = gm / POS;
        int pos = gm % POS;
        #pragma unroll
        for (int n = 0; n < TN; n++) {
            int gj = col0 + tx*TN + n;
            float v = acc[m][n] + bias[gj];
            int t = gj >> 8;
            int h = (gj >> 5) & 7;
            int d = gj & 31;
            long off = ((long)(b*NH + h)*POS + pos)*HD + d;
            if (t == 0)       g_q[off] = v * QSCALE;
            else if (t == 1)  g_k[off] = v;
            else              g_v[off] = v;
        }
    }
}

// Projection GEMM: g_att [TOK,256] @ w_proj [256,256] + b_proj -> out
__global__ void proj_gemm_kernel(const float* __restrict__ Bw,
                                 const float* __restrict__ bias,
                                 float* __restrict__ Cout)
{
    __shared__ float As[BK][BM+4];
    __shared__ float Bs[BK][BN+4];

    const int tid  = threadIdx.x;
    const int row0 = blockIdx.y * BM;
    const int col0 = blockIdx.x * BN;
    const int K = C_;
    const int N = C_;

    float acc[TM][TN];
    #pragma unroll
    for (int m = 0; m < TM; m++)
        #pragma unroll
        for (int n = 0; n < TN; n++)
            acc[m][n] = 0.0f;

    const int ty = tid / 16;
    const int tx = tid % 16;

    for (int k0 = 0; k0 < K; k0 += BK) {
        #pragma unroll
        for (int j = 0; j < (BM*BK)/256; j++) {
            int i = tid + j*256;
            int r = i / BK, c = i % BK;
            As[c][r] = g_att[(long)(row0 + r)*K + (k0 + c)];
        }
        #pragma unroll
        for (int j = 0; j < (BK*BN)/256; j++) {
            int i = tid + j*256;
            int r = i / BN, c = i % BN;
            Bs[r][c] = Bw[(long)(k0 + r)*N + (col0 + c)];
        }
        __syncthreads();

        #pragma unroll
        for (int kk = 0; kk < BK; kk++) {
            float ra[TM], rb[TN];
            #pragma unroll
            for (int m = 0; m < TM; m++) ra[m] = As[kk][ty*TM + m];
            #pragma unroll
            for (int n = 0; n < TN; n++) rb[n] = Bs[kk][tx*TN + n];
            #pragma unroll
            for (int m = 0; m < TM; m++)
                #pragma unroll
                for (int n = 0; n < TN; n++)
                    acc[m][n] += ra[m] * rb[n];
        }
        __syncthreads();
    }

    #pragma unroll
    for (int m = 0; m < TM; m++) {
        int gm = row0 + ty*TM + m;
        #pragma unroll
        for (int n = 0; n < TN; n++) {
            int gj = col0 + tx*TN + n;
            Cout[(long)gm*N + gj] = acc[m][n] + bias[gj];
        }
    }
}

// ---------------------------------------------------------------------------
// Neighborhood attention: one warp per (token, head). lane = head-dim.
// 49 neighbors (7x7 window, always fully inside thanks to NATTEN clamping).
// ---------------------------------------------------------------------------
__global__ void natten_kernel(const float* __restrict__ rpb0,
                              const float* __restrict__ rpb1)
{
    const int m    = blockIdx.x;            // token index
    const int warp = threadIdx.x >> 5;      // head
    const int lane = threadIdx.x & 31;      // head-dim

    const int h   = warp;
    const int b   = m / POS;
    const int pos = m % POS;
    const int y   = pos / WW;
    const int x   = pos % WW;

    const int dil = (h < 4) ? 1 : 2;
    const float* __restrict__ rpb = (h < 4) ? rpb0 : rpb1;
    const int hh  = (h < 4) ? h : (h - 4);

    int nb_y[7], bi_y[7], nb_x[7], bi_x[7];
    {
        int r = y % dil, p = y / dil;
        int Lr = (HH - r + dil - 1) / dil;
        int ps = p - 3;
        if (ps < 0) ps = 0;
        if (ps > Lr - 7) ps = Lr - 7;
        #pragma unroll
        for (int a = 0; a < 7; a++) { nb_y[a] = (ps + a)*dil + r; bi_y[a] = a + (ps - p) + 6; }
    }
    {
        int r = x % dil, p = x / dil;
        int Lr = (WW - r + dil - 1) / dil;
        int ps = p - 3;
        if (ps < 0) ps = 0;
        if (ps > Lr - 7) ps = Lr - 7;
        #pragma unroll
        for (int a = 0; a < 7; a++) { nb_x[a] = (ps + a)*dil + r; bi_x[a] = a + (ps - p) + 6; }
    }

    const long base = (long)(b*NH + h) * POS * HD;
    const float qv = g_q[base + (long)pos*HD + lane];

    float l0 = -1e30f, l1 = -1e30f;

    #pragma unroll
    for (int i = 0; i < 7; i++) {
        #pragma unroll
        for (int j = 0; j < 7; j++) {
            int kp = nb_y[i]*WW + nb_x[j];
            float d = qv * g_k[base + (long)kp*HD + lane];
            #pragma unroll
            for (int s = 16; s; s >>= 1)
                d += __shfl_xor_sync(0xffffffffu, d, s);
            d += rpb[hh*169 + bi_y[i]*13 + bi_x[j]];
            int nb = i*7 + j;
            if (nb < 32) { if (lane == nb)      l0 = d; }
            else         { if (lane == nb - 32) l1 = d; }
        }
    }

    // softmax over 49 logits (l0 on all lanes, l1 on lanes 0..16)
    float mx = fmaxf(l0, l1);
    #pragma unroll
    for (int s = 16; s; s >>= 1)
        mx = fmaxf(mx, __shfl_xor_sync(0xffffffffu, mx, s));

    float p0 = __expf(l0 - mx);
    float p1 = __expf(l1 - mx);   // -1e30 -> underflows to 0

    float sum = p0 + p1;
    #pragma unroll
    for (int s = 16; s; s >>= 1)
        sum += __shfl_xor_sync(0xffffffffu, sum, s);
    const float inv = 1.0f / sum;

    float acc = 0.0f;
    #pragma unroll
    for (int nb = 0; nb < 49; nb++) {
        int i = nb / 7, j = nb % 7;
        int kp = nb_y[i]*WW + nb_x[j];
        float pv = (nb < 32) ? p0 : p1;
        float p  = __shfl_sync(0xffffffffu, pv, nb & 31);
        acc += p * g_v[base + (long)kp*HD + lane];
    }

    g_att[(long)(b*POS + pos)*C_ + h*HD + lane] = acc * inv;
}

// ---------------------------------------------------------------------------
extern "C" void kernel_launch(void* const* d_in, const int* in_sizes, int n_in,
                              void* d_out, int out_size)
{
    const float* x      = (const float*)d_in[0];
    const float* w_qkv  = (const float*)d_in[1];
    const float* b_qkv  = (const float*)d_in[2];
    const float* w_proj = (const float*)d_in[3];
    const float* b_proj = (const float*)d_in[4];
    const float* rpb0   = (const float*)d_in[5];
    const float* rpb1   = (const float*)d_in[6];
    float* out = (float*)d_out;

    dim3 blk(256);
    dim3 grid_qkv((3*C_)/BN, TOK/BM);   // (12, 98)
    dim3 grid_proj(C_/BN,    TOK/BM);   // (4, 98)

    qkv_gemm_kernel<<<grid_qkv, blk>>>(x, w_qkv, b_qkv);
    natten_kernel<<<TOK, 256>>>(rpb0, rpb1);
    proj_gemm_kernel<<<grid_proj, blk>>>(w_proj, b_proj, out);
}